// round 3
// baseline (speedup 1.0000x reference)
#include <cuda_runtime.h>
#include <cuda_bf16.h>
#include <math.h>

// Problem constants
#define B_ 4
#define S_ 2048
#define DIN 2048
#define DOUT 2048
#define DEPTH 11
#define NLEV (DEPTH + 1)          // 12 levels
#define NNODES 4095
#define NTOK (B_ * S_)            // 8192 tokens
#define NLEAF 2048
#define LEAF0 2047

#define TRAV_BLOCKS (NTOK / 4)    // 4 tokens per 256-thread CTA (2 warps/token)
#define TRN_BX 128                // transpose grid x: ceil(4095/32)
#define TRN_BY 64                 // transpose grid y: 2048/32
#define TRN_BLOCKS (TRN_BX * TRN_BY)

// Static scratch
__device__ float          g_wout_t[(size_t)NNODES * DOUT];
__device__ float          g_gel[NTOK * NLEV];
__device__ unsigned short g_nodes[NTOK * NLEV];
__device__ int            g_hist[NLEAF];
__device__ int            g_perm[NTOK];

__device__ __forceinline__ float gelu_exact(float s) {
    return 0.5f * s * (1.0f + erff(s * 0.70710678118654752440f));
}

// ---------------------------------------------------------------------------
// Fused kernel: blocks [0, TRAV_BLOCKS) traverse; the rest transpose w_out.
// Transpose (DRAM-bound) overlaps traversal (L2/latency-bound).
// ---------------------------------------------------------------------------
__global__ __launch_bounds__(256, 4) void traverse_and_transpose_kernel(
    const float* __restrict__ x,
    const float* __restrict__ w_in,
    const float* __restrict__ w_out)
{
    __shared__ float smem_tile[32][33];        // transpose path
    __shared__ float halves[2][4][2];          // traverse path (double-buffered)

    if (blockIdx.x >= TRAV_BLOCKS) {
        // -------- transpose partition --------
        const int tb  = blockIdx.x - TRAV_BLOCKS;
        const int nx0 = (tb % TRN_BX) * 32;    // node dim
        const int dy0 = (tb / TRN_BX) * 32;    // dout dim
        const int tx  = threadIdx.x & 31;
        const int ty  = threadIdx.x >> 5;      // 0..7
#pragma unroll
        for (int j = 0; j < 32; j += 8) {
            int r = dy0 + ty + j, c = nx0 + tx;
            float v = 0.0f;
            if (c < NNODES) v = w_out[(size_t)r * NNODES + c];
            smem_tile[ty + j][tx] = v;
        }
        __syncthreads();
#pragma unroll
        for (int j = 0; j < 32; j += 8) {
            int r = nx0 + ty + j, c = dy0 + tx;
            if (r < NNODES) g_wout_t[(size_t)r * DOUT + c] = smem_tile[tx][ty + j];
        }
        return;
    }

    // -------- traverse partition: 2 warps per token --------
    const int pair = threadIdx.x >> 6;         // 0..3 within CTA
    const int h    = (threadIdx.x >> 5) & 1;   // half index
    const int lane = threadIdx.x & 31;
    const int tok  = blockIdx.x * 4 + pair;

    // load this warp's half of x: 8 x float4 (h selects float4s [h*256, h*256+256))
    const float4* __restrict__ xr4 =
        reinterpret_cast<const float4*>(x + (size_t)tok * DIN) + h * 256;
    float4 xr[8];
#pragma unroll
    for (int j = 0; j < 8; j++) xr[j] = xr4[j * 32 + lane];

    int cur = 0;
#pragma unroll
    for (int l = 0; l < NLEV; l++) {
        const float4* __restrict__ w =
            reinterpret_cast<const float4*>(w_in + (size_t)cur * DIN) + h * 256;
        float p0 = 0.f, p1 = 0.f;
#pragma unroll
        for (int j = 0; j < 8; j += 2) {
            float4 a = w[(j + 0) * 32 + lane];
            float4 b = w[(j + 1) * 32 + lane];
            p0 += xr[j + 0].x * a.x + xr[j + 0].y * a.y + xr[j + 0].z * a.z + xr[j + 0].w * a.w;
            p1 += xr[j + 1].x * b.x + xr[j + 1].y * b.y + xr[j + 1].z * b.z + xr[j + 1].w * b.w;
        }
        float p = p0 + p1;
#pragma unroll
        for (int off = 16; off > 0; off >>= 1)
            p += __shfl_xor_sync(0xffffffffu, p, off);
        if (lane == 0) halves[l & 1][pair][h] = p;
        __syncthreads();
        p = halves[l & 1][pair][0] + halves[l & 1][pair][1];

        if (h == 0 && lane == 0) {
            g_nodes[tok * NLEV + l] = (unsigned short)cur;
            g_gel[tok * NLEV + l]   = gelu_exact(p);
        }
        cur = cur * 2 + (p >= 0.0f ? 2 : 1);
    }
    if (h == 0 && lane == 0) {
        int leaf = (cur - 1) >> 1;     // level-11 node
        atomicAdd(&g_hist[leaf - LEAF0], 1);
    }
}

// ---------------------------------------------------------------------------
// Fused scan + scatter, one CTA of 1024 threads.
// ---------------------------------------------------------------------------
__global__ __launch_bounds__(1024) void scan_scatter_kernel() {
    __shared__ int s0[NLEAF];
    __shared__ int s1[NLEAF];
    const int t = threadIdx.x;
    s0[t]        = g_hist[t];
    s0[t + 1024] = g_hist[t + 1024];
    __syncthreads();
    int* src = s0; int* dst = s1;
    for (int off = 1; off < NLEAF; off <<= 1) {
#pragma unroll
        for (int k = 0; k < 2; k++) {
            int i = t + k * 1024;
            int v = src[i];
            if (i >= off) v += src[i - off];
            dst[i] = v;
        }
        __syncthreads();
        int* tmp = src; src = dst; dst = tmp;
    }
    // src = inclusive scan; turn into exclusive bases (in dst, reused)
#pragma unroll
    for (int k = 0; k < 2; k++) {
        int i = t + k * 1024;
        dst[i] = (i == 0) ? 0 : src[i - 1];
    }
    __syncthreads();
    // scatter: 8 tokens per thread, smem atomics on bases
#pragma unroll
    for (int k = 0; k < 8; k++) {
        int tok  = t + k * 1024;
        int leaf = (int)g_nodes[tok * NLEV + DEPTH] - LEAF0;
        int pos  = atomicAdd(&dst[leaf], 1);
        g_perm[pos] = tok;
    }
}

// ---------------------------------------------------------------------------
// Accumulate: 2 warps per (leaf-sorted) token, metadata in smem.
// ---------------------------------------------------------------------------
__global__ __launch_bounds__(256, 4) void accum_kernel(float* __restrict__ out) {
    __shared__ int   s_tok[4];
    __shared__ int   s_node[4][NLEV];
    __shared__ float s_gel[4][NLEV];

    const int pair = threadIdx.x >> 6;
    const int h    = (threadIdx.x >> 5) & 1;
    const int lane = threadIdx.x & 31;

    if (threadIdx.x < 4) s_tok[threadIdx.x] = g_perm[blockIdx.x * 4 + threadIdx.x];
    __syncthreads();
    if (threadIdx.x < 48) {
        int p = threadIdx.x / NLEV, l = threadIdx.x % NLEV;
        int tk = s_tok[p];
        s_node[p][l] = (int)g_nodes[tk * NLEV + l];
        s_gel[p][l]  = g_gel[tk * NLEV + l];
    }
    __syncthreads();

    float4 acc[8];
#pragma unroll
    for (int j = 0; j < 8; j++) acc[j] = make_float4(0.f, 0.f, 0.f, 0.f);

#pragma unroll
    for (int l = 0; l < NLEV; l++) {
        const int   node = s_node[pair][l];
        const float gl   = s_gel[pair][l];
        const float4* __restrict__ w =
            reinterpret_cast<const float4*>(g_wout_t + (size_t)node * DOUT) + h * 256;
#pragma unroll
        for (int j = 0; j < 8; j++) {
            float4 wv = w[j * 32 + lane];
            acc[j].x += gl * wv.x;
            acc[j].y += gl * wv.y;
            acc[j].z += gl * wv.z;
            acc[j].w += gl * wv.w;
        }
    }

    const int tok = s_tok[pair];
    float4* __restrict__ o = reinterpret_cast<float4*>(out + (size_t)tok * DOUT) + h * 256;
#pragma unroll
    for (int j = 0; j < 8; j++) o[j * 32 + lane] = acc[j];
}

// ---------------------------------------------------------------------------
extern "C" void kernel_launch(void* const* d_in, const int* in_sizes, int n_in,
                              void* d_out, int out_size) {
    const float* x     = (const float*)d_in[0];
    const float* w_in  = (const float*)d_in[1];
    const float* w_out = (const float*)d_in[2];
    float* out = (float*)d_out;

    void* hist_ptr;
    cudaGetSymbolAddress(&hist_ptr, g_hist);
    cudaMemsetAsync(hist_ptr, 0, NLEAF * sizeof(int));

    traverse_and_transpose_kernel<<<TRAV_BLOCKS + TRN_BLOCKS, 256>>>(x, w_in, w_out);
    scan_scatter_kernel<<<1, 1024>>>();
    accum_kernel<<<NTOK / 4, 256>>>(out);
}